// round 13
// baseline (speedup 1.0000x reference)
#include <cuda_runtime.h>
#include <cuda_bf16.h>

// Problem constants:
//   T=4 tables, E=1,000,000 rows/table, D=128 dim, B=8192 bags, L=32 bag length
//   indices: [T, B, L] int32 (1,048,576 elems)
//   weights: [T, E, D] float32 (512,000,000 elems)
//   output:  [B, T*D] float32: out[b, t*D + d] = sum_l weights[t, indices[t,b,l], d]

#define T_TABLES 4
#define E_ROWS   1000000
#define D_DIM    128
#define B_BATCH  8192
#define L_BAG    32
#define BATCH    16          // rows buffered per stage (16 x float4 regs of MLP)
#define NUM_SMS  148
#define CTAS_PER_SM 3
#define NUM_CTAS (NUM_SMS * CTAS_PER_SM)     // 444 -> exactly one wave
#define WARPS_PER_CTA 8
#define TOTAL_BAGS (T_TABLES * B_BATCH)      // 32768

// Persistent warp-per-bag kernel. Lane k owns float4 chunk k of the D=128 row.
// Each lane loads one bag index (int32, 128B coalesced/warp, clamped once);
// row indices shuffle-broadcast; gathers software-batched 16-deep for
// front-batched independent LDG.128s. Grid is exactly one wave (444 CTAs) so
// there is no tail-wave SM idling and no wave transitions; the next bag's
// index vector is prefetched before the current bag's gather/accumulate so
// the only inter-bag serial dependency is off the critical path. No inter-CTA
// communication: grid-stride covers all bags for any residency.
__global__ __launch_bounds__(256, CTAS_PER_SM)
void embedding_bag_sum_kernel(const int* __restrict__ indices,
                              const float* __restrict__ weights,
                              float* __restrict__ out)
{
    const int lane = threadIdx.x & 31;
    const int warp0 = (blockIdx.x * WARPS_PER_CTA) + (threadIdx.x >> 5);
    const int stride = NUM_CTAS * WARPS_PER_CTA;   // 3552 warps total

    float4* out4 = reinterpret_cast<float4*>(out);

    int bag = warp0;
    if (bag >= TOTAL_BAGS) return;

    int my_idx = __ldg(indices + (size_t)bag * L_BAG + lane);

    while (bag < TOTAL_BAGS) {
        const int next = bag + stride;
        // Prefetch next bag's indices early so the load overlaps this bag's
        // gathers instead of serializing between bag iterations.
        int next_idx = 0;
        if (next < TOTAL_BAGS)
            next_idx = __ldg(indices + (size_t)next * L_BAG + lane);

        // Clamp once per lane: malformed index degrades to rel_err, not a crash.
        if ((unsigned)my_idx >= (unsigned)E_ROWS) my_idx = 0;

        const int t = bag >> 13;                  // bag / B  (B = 8192 = 2^13)
        const int b = bag & (B_BATCH - 1);        // bag % B

        const float4* wt = reinterpret_cast<const float4*>(
            weights + (size_t)t * E_ROWS * D_DIM);

        float4 acc = make_float4(0.f, 0.f, 0.f, 0.f);

        #pragma unroll
        for (int stage = 0; stage < L_BAG / BATCH; ++stage) {
            float4 v[BATCH];
            #pragma unroll
            for (int j = 0; j < BATCH; ++j) {
                int row = __shfl_sync(0xffffffffu, my_idx, stage * BATCH + j);
                v[j] = __ldg(wt + (size_t)row * (D_DIM / 4) + lane);
            }
            #pragma unroll
            for (int j = 0; j < BATCH; ++j) {
                acc.x += v[j].x;
                acc.y += v[j].y;
                acc.z += v[j].z;
                acc.w += v[j].w;
            }
        }

        // out[b, t*D + d] as float4: index = b*128 + t*32 + lane
        out4[(size_t)b * (T_TABLES * D_DIM / 4) + t * (D_DIM / 4) + lane] = acc;

        my_idx = next_idx;
        bag = next;
    }
}

extern "C" void kernel_launch(void* const* d_in, const int* in_sizes, int n_in,
                              void* d_out, int out_size)
{
    // Identify inputs by element count (robust to metadata ordering):
    //   indices: T*B*L = 1,048,576 ; weights: T*E*D = 512,000,000
    const int*   indices;
    const float* weights;
    if (in_sizes[0] < in_sizes[1]) {
        indices = (const int*)d_in[0];
        weights = (const float*)d_in[1];
    } else {
        indices = (const int*)d_in[1];
        weights = (const float*)d_in[0];
    }
    float* out = (float*)d_out;

    embedding_bag_sum_kernel<<<NUM_CTAS, 256>>>(indices, weights, out);
}

// round 14
// speedup vs baseline: 1.1023x; 1.1023x over previous
#include <cuda_runtime.h>
#include <cuda_bf16.h>

// Problem constants:
//   T=4 tables, E=1,000,000 rows/table, D=128 dim, B=8192 bags, L=32 bag length
//   indices: [T, B, L] int32 (1,048,576 elems)
//   weights: [T, E, D] float32 (512,000,000 elems)
//   output:  [B, T*D] float32: out[b, t*D + d] = sum_l weights[t, indices[t,b,l], d]
//
// Design (converged after R5-R13 exploration):
//   - One warp per (t,b) bag; lane k owns float4 chunk k of the D=128 row
//     -> every weight-row read is one fully-coalesced 512B LDG.128 per warp.
//   - Bag indices: one int32 per lane (128B coalesced), shuffle-broadcast.
//   - Gathers software-batched 16-deep into a register buffer so ptxas
//     front-batches 16 independent LDG.128s per warp (deep MLP).
//   - Flat 4096-CTA grid (NOT persistent): CTA exit + hardware work-steal is
//     the cheapest pipeline refill; persistent grids serialize per-warp bags
//     and cost ~10us (measured R13).
//   - Measured: 78.6us, 6.38 TB/s (80.5% of HBM spec), traffic at the
//     compulsory minimum (~500MB). This is the random-gather ceiling.

#define T_TABLES 4
#define E_ROWS   1000000
#define D_DIM    128
#define B_BATCH  8192
#define L_BAG    32
#define BATCH    16  // rows buffered per stage (16 x float4 = 64 regs of MLP)

__global__ __launch_bounds__(256, 3)
void embedding_bag_sum_kernel(const int* __restrict__ indices,
                              const float* __restrict__ weights,
                              float* __restrict__ out)
{
    const int gtid = blockIdx.x * blockDim.x + threadIdx.x;
    const int warp = gtid >> 5;               // 0 .. T*B-1 (grid is exact)
    const int lane = threadIdx.x & 31;

    const int t = warp >> 13;                 // warp / B  (B = 8192 = 2^13)
    const int b = warp & (B_BATCH - 1);       // warp % B

    const int* bag = indices + ((size_t)t * B_BATCH + b) * L_BAG;
    int my_idx = __ldg(bag + lane);
    // Clamp once per lane: malformed index degrades to rel_err, not a crash.
    if ((unsigned)my_idx >= (unsigned)E_ROWS) my_idx = 0;

    const float4* wt = reinterpret_cast<const float4*>(
        weights + (size_t)t * E_ROWS * D_DIM);

    float4 acc = make_float4(0.f, 0.f, 0.f, 0.f);

    #pragma unroll
    for (int stage = 0; stage < L_BAG / BATCH; ++stage) {
        float4 v[BATCH];
        #pragma unroll
        for (int j = 0; j < BATCH; ++j) {
            int row = __shfl_sync(0xffffffffu, my_idx, stage * BATCH + j);
            v[j] = __ldg(wt + (size_t)row * (D_DIM / 4) + lane);
        }
        #pragma unroll
        for (int j = 0; j < BATCH; ++j) {
            acc.x += v[j].x;
            acc.y += v[j].y;
            acc.z += v[j].z;
            acc.w += v[j].w;
        }
    }

    // out[b, t*D + d] as float4: index = b*128 + t*32 + lane
    float4* out4 = reinterpret_cast<float4*>(out);
    out4[(size_t)b * (T_TABLES * D_DIM / 4) + t * (D_DIM / 4) + lane] = acc;
}

extern "C" void kernel_launch(void* const* d_in, const int* in_sizes, int n_in,
                              void* d_out, int out_size)
{
    // Identify inputs by element count (robust to metadata ordering):
    //   indices: T*B*L = 1,048,576 ; weights: T*E*D = 512,000,000
    const int*   indices;
    const float* weights;
    if (in_sizes[0] < in_sizes[1]) {
        indices = (const int*)d_in[0];
        weights = (const float*)d_in[1];
    } else {
        indices = (const int*)d_in[1];
        weights = (const float*)d_in[0];
    }
    float* out = (float*)d_out;

    const int total_warps = T_TABLES * B_BATCH;           // 32768
    const int threads     = 256;                          // 8 warps/CTA
    const int blocks      = (total_warps * 32) / threads; // 4096

    embedding_bag_sum_kernel<<<blocks, threads>>>(indices, weights, out);
}

// round 15
// speedup vs baseline: 1.1312x; 1.0262x over previous
#include <cuda_runtime.h>
#include <cuda_bf16.h>

// Problem constants:
//   T=4 tables, E=1,000,000 rows/table, D=128 dim, B=8192 bags, L=32 bag length
//   indices: [T, B, L] int32 (1,048,576 elems)
//   weights: [T, E, D] float32 (512,000,000 elems)
//   output:  [B, T*D] float32: out[b, t*D + d] = sum_l weights[t, indices[t,b,l], d]
//
// Design (converged after R5-R14 exploration):
//   - One warp per (t,b) bag; lane k owns float4 chunk k of the D=128 row
//     -> every weight-row read is one fully-coalesced 512B LDG.128 per warp.
//   - Bag indices: one int32 per lane (128B coalesced, __ldcs read-once),
//     shuffle-broadcast to the warp.
//   - Gathers software-batched 16-deep into a register buffer so ptxas
//     front-batches 16 independent LDG.128s per warp (deep MLP).
//   - Flat 4096-CTA grid (NOT persistent): CTA exit + hardware work-steal is
//     the cheapest pipeline refill; a persistent one-wave grid serialized
//     per-warp bag drains and cost ~10us (measured R13).
//   - Output stored with __stcs (evict-first): write-once lines stay out of
//     the L2 window so more capacity serves duplicate weight-row dedup.
//   - Measured plateau: ~78.6-80.3us, ~6.35 TB/s (≈80% of HBM spec), traffic
//     at the compulsory minimum (~500MB) -> random-gather ceiling.

#define T_TABLES 4
#define E_ROWS   1000000
#define D_DIM    128
#define B_BATCH  8192
#define L_BAG    32
#define BATCH    16  // rows buffered per stage (16 x float4 = 64 regs of MLP)

__global__ __launch_bounds__(256, 3)
void embedding_bag_sum_kernel(const int* __restrict__ indices,
                              const float* __restrict__ weights,
                              float* __restrict__ out)
{
    const int gtid = blockIdx.x * blockDim.x + threadIdx.x;
    const int warp = gtid >> 5;               // 0 .. T*B-1 (grid is exact)
    const int lane = threadIdx.x & 31;

    const int t = warp >> 13;                 // warp / B  (B = 8192 = 2^13)
    const int b = warp & (B_BATCH - 1);       // warp % B

    // Read-once index vector: streaming load (evict-first).
    const int* bag = indices + ((size_t)t * B_BATCH + b) * L_BAG;
    int my_idx = __ldcs(bag + lane);
    // Clamp once per lane: malformed index degrades to rel_err, not a crash.
    if ((unsigned)my_idx >= (unsigned)E_ROWS) my_idx = 0;

    const float4* wt = reinterpret_cast<const float4*>(
        weights + (size_t)t * E_ROWS * D_DIM);

    float4 acc = make_float4(0.f, 0.f, 0.f, 0.f);

    #pragma unroll
    for (int stage = 0; stage < L_BAG / BATCH; ++stage) {
        float4 v[BATCH];
        #pragma unroll
        for (int j = 0; j < BATCH; ++j) {
            int row = __shfl_sync(0xffffffffu, my_idx, stage * BATCH + j);
            // Default cache policy: L2 retention is what dedups the ~12%
            // duplicate rows across concurrent bags.
            v[j] = __ldg(wt + (size_t)row * (D_DIM / 4) + lane);
        }
        #pragma unroll
        for (int j = 0; j < BATCH; ++j) {
            acc.x += v[j].x;
            acc.y += v[j].y;
            acc.z += v[j].z;
            acc.w += v[j].w;
        }
    }

    // out[b, t*D + d] as float4: index = b*128 + t*32 + lane.
    // Streaming store: write-once, never re-read -> evict-first keeps L2
    // capacity for weight-row dedup.
    float4* out4 = reinterpret_cast<float4*>(out);
    __stcs(out4 + (size_t)b * (T_TABLES * D_DIM / 4) + t * (D_DIM / 4) + lane,
           acc);
}

extern "C" void kernel_launch(void* const* d_in, const int* in_sizes, int n_in,
                              void* d_out, int out_size)
{
    // Identify inputs by element count (robust to metadata ordering):
    //   indices: T*B*L = 1,048,576 ; weights: T*E*D = 512,000,000
    const int*   indices;
    const float* weights;
    if (in_sizes[0] < in_sizes[1]) {
        indices = (const int*)d_in[0];
        weights = (const float*)d_in[1];
    } else {
        indices = (const int*)d_in[1];
        weights = (const float*)d_in[0];
    }
    float* out = (float*)d_out;

    const int total_warps = T_TABLES * B_BATCH;           // 32768
    const int threads     = 256;                          // 8 warps/CTA
    const int blocks      = (total_warps * 32) / threads; // 4096

    embedding_bag_sum_kernel<<<blocks, threads>>>(indices, weights, out);
}